// round 6
// baseline (speedup 1.0000x reference)
#include <cuda_runtime.h>
#include <cuda_bf16.h>
#include <cuda_fp8.h>
#include <stdint.h>

// out[m] = x[m]·W + b + 0.5*||x[m]V||^2 - 0.5*(sum_i x[m,i])^2 * ||V.sum(0)||^2
// x: (16384,4096) f32, W: (1,4096) f32, b: (1,) f32, V: (4096,128) f32, out f32.
// GEMM in fp8 e4m3 (V pre-scaled by 512), side sums exact fp32.

#define MROWS 16384
#define KDIM  4096
#define NDIM  128
#define KC    64                     // K per chunk
#define NCH   (KDIM / KC)            // 64
#define RSTRIDE 80                   // smem row stride bytes (64B data + 16B pad)
#define TILEB (128 * RSTRIDE)        // 10240 B per buffer

#define OF_B   (2 * TILEB)           // 20480
#define OF_RED (4 * TILEB)           // 40960
#define OF_SXS (OF_RED + 1024)
#define OF_SWS (OF_SXS + 512)
#define SMEM_TOTAL (OF_SWS + 512)    // 43008 (static shared)

#define VSCALE 512.0f
#define T1SCALE (0.5f / (VSCALE * VSCALE))

__device__ unsigned char g_Vf8[(size_t)NCH * NDIM * KC];  // chunk-major [c][n][kk], e4m3 of 512*V^T
__device__ float g_spart[64 * NDIM];
__device__ float g_s2;

// ---------------- helpers ----------------

static __device__ __forceinline__ uint32_t smem_u32(const void* p) {
    uint32_t r;
    asm("{ .reg .u64 t; cvta.to.shared.u64 t, %1; cvt.u32.u64 %0, t; }"
        : "=r"(r) : "l"(p));
    return r;
}

// pack float4 -> 4 e4m3 bytes (little-endian k order)
static __device__ __forceinline__ uint32_t pack4_e4m3(float4 q) {
    uint16_t lo, hi;
    asm("cvt.rn.satfinite.e4m3x2.f32 %0, %1, %2;" : "=h"(lo) : "f"(q.y), "f"(q.x));
    asm("cvt.rn.satfinite.e4m3x2.f32 %0, %1, %2;" : "=h"(hi) : "f"(q.w), "f"(q.z));
    uint32_t r;
    asm("mov.b32 %0, {%1, %2};" : "=r"(r) : "h"(lo), "h"(hi));
    return r;
}

#define MMA_FP8(d, a0, a1, a2, a3, b0, b1)                                 \
    asm volatile(                                                          \
        "mma.sync.aligned.m16n8k32.row.col.f32.e4m3.e4m3.f32 "             \
        "{%0,%1,%2,%3}, {%4,%5,%6,%7}, {%8,%9}, {%0,%1,%2,%3};"            \
        : "+f"((d)[0]), "+f"((d)[1]), "+f"((d)[2]), "+f"((d)[3])           \
        : "r"(a0), "r"(a1), "r"(a2), "r"(a3), "r"(b0), "r"(b1))

#define LDSM_X4(r0, r1, r2, r3, addr)                                      \
    asm volatile("ldmatrix.sync.aligned.m8n8.x4.shared.b16 "               \
                 "{%0,%1,%2,%3}, [%4];"                                    \
                 : "=r"(r0), "=r"(r1), "=r"(r2), "=r"(r3) : "r"(addr))

// ---------------- prep kernels ----------------

// 64 blocks: block b handles chunk b (K-rows [64b,64b+64)).
// Coalesced V read, fp32 partial column sums, e4m3(512*v) transpose to chunk-major.
__global__ void prep_kernel(const float* __restrict__ V) {
    __shared__ __align__(16) unsigned char sm[128 * RSTRIDE];
    __shared__ float ps[256];
    const int t = threadIdx.x;
    const int b = blockIdx.x;
    const int k0 = b * 64;
    const int n = t & 127;
    const int half = t >> 7;

    float partial = 0.f;
#pragma unroll
    for (int i = 0; i < 32; i++) {
        int kk = 2 * i + half;
        float v = V[(size_t)(k0 + kk) * NDIM + n];
        partial += v;
        __nv_fp8_e4m3 f8(v * VSCALE);
        sm[n * RSTRIDE + kk] = f8.__x;
    }
    ps[t] = partial;
    __syncthreads();
    if (t < 128) g_spart[b * 128 + t] = ps[t] + ps[t + 128];

    // coalesced out: thread t covers 32B of row r
    const int r = t >> 1, part = t & 1;
    const uint4* src = (const uint4*)(sm + r * RSTRIDE + part * 32);
    uint4 u0 = src[0], u1 = src[1];
    uint4* dst = (uint4*)(g_Vf8 + (size_t)b * 8192 + r * 64 + part * 32);
    dst[0] = u0; dst[1] = u1;
}

__global__ void s2_kernel() {
    __shared__ float sh[128];
    int t = threadIdx.x;
    float s = 0.f;
    for (int b2 = 0; b2 < 64; b2++) s += g_spart[b2 * 128 + t];
    sh[t] = s * s;
    __syncthreads();
    for (int o = 64; o > 0; o >>= 1) {
        if (t < o) sh[t] += sh[t + o];
        __syncthreads();
    }
    if (t == 0) g_s2 = sh[0];
}

// ---------------- main kernel ----------------
// 256 thr = 8 warps = 4 m-strips (m32) x 2 n-halves (n64). CTA tile 128x128.
// Homogeneous warps (round-4 structure): LDG prefetch -> fp32 sums -> e4m3 STS
// -> ldmatrix -> fp8 HMMA, double-buffered smem.

__global__ void __launch_bounds__(256, 1) fm_main(
    const float* __restrict__ x, const float* __restrict__ W,
    const float* __restrict__ bias, float* __restrict__ out)
{
    __shared__ __align__(16) char smem[SMEM_TOTAL];
    float (*red)[2] = (float(*)[2])(smem + OF_RED);
    float* sxs = (float*)(smem + OF_SXS);
    float* sws = (float*)(smem + OF_SWS);

    const int t = threadIdx.x;
    const int wid = t >> 5, lane = t & 31;
    const int mstrip = wid & 3;
    const int nhalf  = wid >> 2;
    const int mbase = blockIdx.x * 128;
    const uint32_t sAu = smem_u32(smem);
    const uint32_t sBu = sAu + OF_B;

    // ---- ldmatrix lane addressing (stride-80 rows: 5r mod 8 covers all banks)
    // A: lanes0-7 rows0-7 k-lo16B, 8-15 rows8-15 k-lo, 16-23 rows0-7 k-hi, 24-31 rows8-15 k-hi
    const uint32_t a_rb = sAu + (uint32_t)(mstrip * 32 + (lane & 15)) * RSTRIDE;
    const uint32_t kha = (uint32_t)(lane >> 4);
    // B: lanes0-7 n0-7 k-lo, 8-15 n0-7 k-hi, 16-23 n8-15 k-lo, 24-31 n8-15 k-hi
    const uint32_t b_rb = sBu + (uint32_t)(nhalf * 64 + ((lane >> 4) << 3) + (lane & 7)) * RSTRIDE;
    const uint32_t khb = (uint32_t)((lane >> 3) & 1);

    // ---- gmem staging (coalesced)
    // A: row = (t>>4) + 16i, floats [(t&15)*4, +4) of each 64-float chunk row
    const float* xb = x + ((size_t)(mbase + (t >> 4)) << 12) + (t & 15) * 4;
    // B: chunk-major fp8, thread covers 32B
    const unsigned char* vb = g_Vf8 + (size_t)t * 32;
    const float4* wp = (const float4*)W + (t & 15);

    // ---- STS addresses
    const uint32_t asts = sAu + (t >> 4) * RSTRIDE + (t & 15) * 4;  // +i*16*RSTRIDE
    const uint32_t bsts = sBu + (t >> 1) * RSTRIDE + (t & 1) * 32;

    float acc[2][8][4];
#pragma unroll
    for (int i = 0; i < 2; i++)
#pragma unroll
        for (int j = 0; j < 8; j++)
#pragma unroll
            for (int k = 0; k < 4; k++) acc[i][j][k] = 0.f;

    float sx[8], sw[8];
#pragma unroll
    for (int i = 0; i < 8; i++) { sx[i] = 0.f; sw[i] = 0.f; }

    float4 areg[8];
    uint4  breg[2];

#define LOADA(c) do {                                                       \
        _Pragma("unroll")                                                   \
        for (int i = 0; i < 8; i++)                                         \
            areg[i] = *(const float4*)(xb + ((size_t)i << 16) + (c) * KC);  \
    } while (0)

#define LOADB(c) do {                                                       \
        breg[0] = *(const uint4*)(vb + (size_t)(c) * 8192);                 \
        breg[1] = *(const uint4*)(vb + (size_t)(c) * 8192 + 16);            \
    } while (0)

#define SUMS_STS(c, buf) do {                                               \
        const float4 w4 = wp[(c) * 16];                                     \
        const uint32_t ao_ = (uint32_t)(buf) * TILEB;                       \
        _Pragma("unroll")                                                   \
        for (int i = 0; i < 8; i++) {                                       \
            const float4 q = areg[i];                                       \
            sx[i] += (q.x + q.y) + (q.z + q.w);                             \
            sw[i] += q.x * w4.x + q.y * w4.y + q.z * w4.z + q.w * w4.w;     \
            const uint32_t p = pack4_e4m3(q);                               \
            asm volatile("st.shared.b32 [%0], %1;"                          \
                         :: "r"(asts + ao_ + i * (16 * RSTRIDE)), "r"(p));  \
        }                                                                   \
        asm volatile("st.shared.v4.b32 [%0], {%1,%2,%3,%4};"                \
                     :: "r"(bsts + ao_), "r"(breg[0].x), "r"(breg[0].y),    \
                        "r"(breg[0].z), "r"(breg[0].w));                    \
        asm volatile("st.shared.v4.b32 [%0], {%1,%2,%3,%4};"                \
                     :: "r"(bsts + ao_ + 16), "r"(breg[1].x),               \
                        "r"(breg[1].y), "r"(breg[1].z), "r"(breg[1].w));    \
    } while (0)

    // prologue: stage chunk 0
    LOADA(0); LOADB(0);
    SUMS_STS(0, 0);
    __syncthreads();

#pragma unroll 1
    for (int c = 0; c < NCH; c++) {
        const bool more = (c + 1 < NCH);
        if (more) { LOADA(c + 1); LOADB(c + 1); }

        const uint32_t ao = (uint32_t)(c & 1) * TILEB;
#pragma unroll
        for (int ks = 0; ks < 2; ks++) {
            const uint32_t offA = (2u * ks + kha) * 16;
            uint32_t afr[2][4];
            LDSM_X4(afr[0][0], afr[0][1], afr[0][2], afr[0][3],
                    a_rb + ao + offA);
            LDSM_X4(afr[1][0], afr[1][1], afr[1][2], afr[1][3],
                    a_rb + ao + offA + 16 * RSTRIDE);
            const uint32_t offB = (2u * ks + khb) * 16;
            uint32_t bfr[8][2];
#pragma unroll
            for (int p = 0; p < 4; p++)
                LDSM_X4(bfr[2*p][0], bfr[2*p][1], bfr[2*p+1][0], bfr[2*p+1][1],
                        b_rb + ao + offB + p * (16 * RSTRIDE));
#pragma unroll
            for (int mt = 0; mt < 2; mt++)
#pragma unroll
                for (int nt = 0; nt < 8; nt++)
                    MMA_FP8(acc[mt][nt], afr[mt][0], afr[mt][1], afr[mt][2],
                            afr[mt][3], bfr[nt][0], bfr[nt][1]);
        }

        if (more) SUMS_STS(c + 1, (c + 1) & 1);
        __syncthreads();
    }

    // ---------------- epilogue ----------------
#pragma unroll
    for (int mt = 0; mt < 2; mt++) {
        float p0 = 0.f, p1 = 0.f;
#pragma unroll
        for (int nt = 0; nt < 8; nt++) {
            p0 += acc[mt][nt][0] * acc[mt][nt][0] + acc[mt][nt][1] * acc[mt][nt][1];
            p1 += acc[mt][nt][2] * acc[mt][nt][2] + acc[mt][nt][3] * acc[mt][nt][3];
        }
        p0 += __shfl_xor_sync(0xffffffffu, p0, 1);
        p0 += __shfl_xor_sync(0xffffffffu, p0, 2);
        p1 += __shfl_xor_sync(0xffffffffu, p1, 1);
        p1 += __shfl_xor_sync(0xffffffffu, p1, 2);
        if ((lane & 3) == 0) {
            red[mstrip * 32 + mt * 16 + (lane >> 2)][nhalf]     = p0;
            red[mstrip * 32 + mt * 16 + 8 + (lane >> 2)][nhalf] = p1;
        }
    }

    // side sums: reduce over 16 threads sharing each row
#pragma unroll
    for (int i = 0; i < 8; i++) {
#pragma unroll
        for (int o = 8; o > 0; o >>= 1) {
            sx[i] += __shfl_xor_sync(0xffffffffu, sx[i], o);
            sw[i] += __shfl_xor_sync(0xffffffffu, sw[i], o);
        }
    }
    if ((t & 15) == 0) {
        const int h = t >> 4;
#pragma unroll
        for (int i = 0; i < 8; i++) {
            sxs[i * 16 + h] = sx[i];
            sws[i * 16 + h] = sw[i];
        }
    }
    __syncthreads();

    if (t < 128) {
        const float t1 = red[t][0] + red[t][1];
        const float s_ = sxs[t];
        out[mbase + t] = sws[t] + bias[0] + T1SCALE * t1 - 0.5f * s_ * s_ * g_s2;
    }
}

// ---------------- launch ----------------

extern "C" void kernel_launch(void* const* d_in, const int* in_sizes, int n_in,
                              void* d_out, int out_size) {
    (void)in_sizes; (void)n_in; (void)out_size;
    const float* x = (const float*)d_in[0];
    const float* W = (const float*)d_in[1];
    const float* b = (const float*)d_in[2];
    const float* V = (const float*)d_in[3];
    float* out = (float*)d_out;

    prep_kernel<<<64, 256>>>(V);
    s2_kernel<<<1, 128>>>();
    fm_main<<<MROWS / 128, 256>>>(x, W, b, out);
}

// round 7
// speedup vs baseline: 1.4101x; 1.4101x over previous
#include <cuda_runtime.h>
#include <cuda_bf16.h>
#include <stdint.h>

// out[m] = x[m]·W + b + 0.5*||x[m]V||^2 - 0.5*(sum_i x[m,i])^2 * ||V.sum(0)||^2
// x: (16384,4096) f32, W: (1,4096) f32, b: (1,) f32, V: (4096,128) f32, out f32.

#define MROWS 16384
#define KDIM  4096
#define NDIM  128
#define KC    64                   // K per chunk
#define NCH   (KDIM / KC)          // 64
#define AROW  144                  // padded smem row stride (bytes)
#define ABUF  (128 * AROW)         // 18432 B per buffer

#define OF_B   (2 * ABUF)
#define OF_RED (4 * ABUF)
#define OF_SXS (OF_RED + 1024)
#define OF_SWS (OF_SXS + 512)
#define SMEM_TOTAL (OF_SWS + 512)  // 75776 B

__device__ __nv_bfloat16 g_Vt[(size_t)NCH * NDIM * KC];  // chunk-major [c][n][kk]
__device__ float g_spart[64 * NDIM];
__device__ float g_s2;

// ---------------- helpers ----------------

static __device__ __forceinline__ uint32_t smem_u32(const void* p) {
    uint32_t r;
    asm("{ .reg .u64 t; cvta.to.shared.u64 t, %1; cvt.u32.u64 %0, t; }"
        : "=r"(r) : "l"(p));
    return r;
}

static __device__ __forceinline__ uint32_t pack2(float lo, float hi) {
    __nv_bfloat162 h = __float22bfloat162_rn(make_float2(lo, hi));
    return *reinterpret_cast<uint32_t*>(&h);
}

#define MMA_OP(d, a0, a1, a2, a3, b0, b1)                                  \
    asm volatile(                                                          \
        "mma.sync.aligned.m16n8k16.row.col.f32.bf16.bf16.f32 "             \
        "{%0,%1,%2,%3}, {%4,%5,%6,%7}, {%8,%9}, {%0,%1,%2,%3};"            \
        : "+f"((d)[0]), "+f"((d)[1]), "+f"((d)[2]), "+f"((d)[3])           \
        : "r"(a0), "r"(a1), "r"(a2), "r"(a3), "r"(b0), "r"(b1))

#define LDSM_X4(r0, r1, r2, r3, addr)                                      \
    asm volatile("ldmatrix.sync.aligned.m8n8.x4.shared.b16 "               \
                 "{%0,%1,%2,%3}, [%4];"                                    \
                 : "=r"(r0), "=r"(r1), "=r"(r2), "=r"(r3) : "r"(addr))

// ---------------- prep kernels ----------------

__global__ void prep_kernel(const float* __restrict__ V) {
    __shared__ __align__(16) __nv_bfloat16 sm[128 * 66];
    __shared__ float ps[256];
    const int t = threadIdx.x;
    const int b = blockIdx.x;
    const int k0 = b * 64;
    const int n = t & 127;
    const int half = t >> 7;

    float partial = 0.f;
#pragma unroll
    for (int i = 0; i < 32; i++) {
        int kk = 2 * i + half;
        float v = V[(size_t)(k0 + kk) * NDIM + n];
        partial += v;
        sm[n * 66 + kk] = __float2bfloat16(v);
    }
    ps[t] = partial;
    __syncthreads();
    if (t < 128) g_spart[b * 128 + t] = ps[t] + ps[t + 128];

    const int r = t >> 1, part = t & 1;
    const uint32_t* src = (const uint32_t*)((const char*)sm + r * 132 + part * 64);
    uint32_t v0[16];
#pragma unroll
    for (int i = 0; i < 16; i++) v0[i] = src[i];
    uint4* dst = (uint4*)((char*)g_Vt + (size_t)b * 16384 + (size_t)r * 128 + part * 64);
#pragma unroll
    for (int i = 0; i < 4; i++)
        dst[i] = make_uint4(v0[4*i], v0[4*i+1], v0[4*i+2], v0[4*i+3]);
}

__global__ void s2_kernel() {
    __shared__ float sh[128];
    int t = threadIdx.x;
    float s = 0.f;
    for (int b2 = 0; b2 < 64; b2++) s += g_spart[b2 * 128 + t];
    sh[t] = s * s;
    __syncthreads();
    for (int o = 64; o > 0; o >>= 1) {
        if (t < o) sh[t] += sh[t + o];
        __syncthreads();
    }
    if (t == 0) g_s2 = sh[0];
}

// ---------------- main kernel ----------------
// 256 thr = 8 warps = 4 m-strips (m32) x 2 n-halves (n64). CTA tile 128x128.
// Round-4 structure + register-level fragment double buffering so LDSM
// (crossbar) overlaps HMMA (tensor) instead of phase-alternating.

__global__ void __launch_bounds__(256, 1) fm_main(
    const float* __restrict__ x, const float* __restrict__ W,
    const float* __restrict__ bias, float* __restrict__ out)
{
    extern __shared__ __align__(16) char smem[];
    float (*red)[2] = (float(*)[2])(smem + OF_RED);
    float* sxs = (float*)(smem + OF_SXS);
    float* sws = (float*)(smem + OF_SWS);

    const int t = threadIdx.x;
    const int wid = t >> 5, lane = t & 31;
    const int mstrip = wid & 3;
    const int nhalf  = wid >> 2;
    const int mbase = blockIdx.x * 128;

    const uint32_t sAu = smem_u32(smem);
    const uint32_t sBu = sAu + OF_B;

    // ---- gmem pointers (coalesced)
    const char* xb = (const char*)x + ((size_t)(mbase + (t >> 4)) << 14) + (t & 15) * 16;
    const char* vb = (const char*)g_Vt + (size_t)t * 16;
    const float4* wp = (const float4*)W + (t & 15);

    // ---- STS addresses (bank-conflict free on 144B rows)
    const uint32_t asts = sAu + (t >> 4) * AROW + (t & 15) * 8;
    const uint32_t bsts = sBu + (t >> 3) * AROW + (t & 7) * 16;

    // ---- ldmatrix addresses
    const uint32_t alds = sAu + (uint32_t)(mstrip * 32 + (lane & 15)) * AROW
                        + (lane >> 4) * 16;
    const uint32_t blds = sBu + (uint32_t)(nhalf * 64 + (lane >> 4) * 8 + (lane & 7)) * AROW
                        + ((lane >> 3) & 1) * 16;

    float acc[2][8][4];
#pragma unroll
    for (int i = 0; i < 2; i++)
#pragma unroll
        for (int j = 0; j < 8; j++)
#pragma unroll
            for (int k = 0; k < 4; k++) acc[i][j][k] = 0.f;

    float sx[8], sw[8];
#pragma unroll
    for (int i = 0; i < 8; i++) { sx[i] = 0.f; sw[i] = 0.f; }

    float4 areg[8];
    uint4  breg[4];

    // fragment double buffer
    uint32_t afr[2][2][4];
    uint32_t bfr[2][8][2];

#define LOADA(c) do {                                                       \
        _Pragma("unroll")                                                   \
        for (int i = 0; i < 8; i++)                                         \
            areg[i] = *(const float4*)(xb + (size_t)i * 262144 + (c) * 256);\
    } while (0)

#define LOADB(c) do {                                                       \
        _Pragma("unroll")                                                   \
        for (int j = 0; j < 4; j++)                                         \
            breg[j] = *(const uint4*)(vb + (size_t)(c) * 16384 + j * 4096); \
    } while (0)

#define SUMS_STS(c, buf) do {                                               \
        const float4 w4 = wp[(c) * 16];                                     \
        const uint32_t ao_ = (uint32_t)(buf) * ABUF;                        \
        _Pragma("unroll")                                                   \
        for (int i = 0; i < 8; i++) {                                       \
            const float4 q = areg[i];                                       \
            sx[i] += (q.x + q.y) + (q.z + q.w);                             \
            sw[i] += q.x * w4.x + q.y * w4.y + q.z * w4.z + q.w * w4.w;     \
            const uint32_t p0 = pack2(q.x, q.y), p1 = pack2(q.z, q.w);      \
            asm volatile("st.shared.v2.b32 [%0], {%1,%2};"                  \
                         :: "r"(asts + ao_ + i * 2304), "r"(p0), "r"(p1));  \
        }                                                                   \
        _Pragma("unroll")                                                   \
        for (int j = 0; j < 4; j++)                                         \
            asm volatile("st.shared.v4.b32 [%0], {%1,%2,%3,%4};"            \
                         :: "r"(bsts + ao_ + j * 4608), "r"(breg[j].x),     \
                            "r"(breg[j].y), "r"(breg[j].z), "r"(breg[j].w));\
    } while (0)

    // load fragments for k-step ks of current chunk into frag buffer fb
#define LDFRAG(fb, ks_) do {                                                \
        const uint32_t off_ = ao + (uint32_t)(ks_) * 32;                    \
        LDSM_X4(afr[fb][0][0], afr[fb][0][1], afr[fb][0][2], afr[fb][0][3], \
                alds + off_);                                               \
        LDSM_X4(afr[fb][1][0], afr[fb][1][1], afr[fb][1][2], afr[fb][1][3], \
                alds + off_ + 16 * AROW);                                   \
        _Pragma("unroll")                                                   \
        for (int p = 0; p < 4; p++)                                         \
            LDSM_X4(bfr[fb][2*p][0], bfr[fb][2*p][1],                       \
                    bfr[fb][2*p+1][0], bfr[fb][2*p+1][1],                   \
                    blds + off_ + p * (16 * AROW));                         \
    } while (0)

#define MMA_STEP(fb) do {                                                   \
        _Pragma("unroll")                                                   \
        for (int mt = 0; mt < 2; mt++)                                      \
            _Pragma("unroll")                                               \
            for (int nt = 0; nt < 8; nt++)                                  \
                MMA_OP(acc[mt][nt], afr[fb][mt][0], afr[fb][mt][1],         \
                       afr[fb][mt][2], afr[fb][mt][3],                      \
                       bfr[fb][nt][0], bfr[fb][nt][1]);                     \
    } while (0)

    // prologue: stage chunk 0
    LOADA(0); LOADB(0);
    SUMS_STS(0, 0);
    __syncthreads();

#pragma unroll 1
    for (int c = 0; c < NCH; c++) {
        const bool more = (c + 1 < NCH);
        if (more) { LOADA(c + 1); LOADB(c + 1); }

        const uint32_t ao = (uint32_t)(c & 1) * ABUF;

        // software-pipelined k-steps: LDSM(ks+1) overlaps MMA(ks)
        LDFRAG(0, 0);
        LDFRAG(1, 1);
        MMA_STEP(0);
        LDFRAG(0, 2);
        MMA_STEP(1);
        LDFRAG(1, 3);
        MMA_STEP(0);
        if (more) SUMS_STS(c + 1, (c + 1) & 1);   // STS in MMA shadow
        MMA_STEP(1);

        __syncthreads();
    }

    // ---------------- epilogue ----------------
#pragma unroll
    for (int mt = 0; mt < 2; mt++) {
        float p0 = 0.f, p1 = 0.f;
#pragma unroll
        for (int nt = 0; nt < 8; nt++) {
            p0 += acc[mt][nt][0] * acc[mt][nt][0] + acc[mt][nt][1] * acc[mt][nt][1];
            p1 += acc[mt][nt][2] * acc[mt][nt][2] + acc[mt][nt][3] * acc[mt][nt][3];
        }
        p0 += __shfl_xor_sync(0xffffffffu, p0, 1);
        p0 += __shfl_xor_sync(0xffffffffu, p0, 2);
        p1 += __shfl_xor_sync(0xffffffffu, p1, 1);
        p1 += __shfl_xor_sync(0xffffffffu, p1, 2);
        if ((lane & 3) == 0) {
            red[mstrip * 32 + mt * 16 + (lane >> 2)][nhalf]     = p0;
            red[mstrip * 32 + mt * 16 + 8 + (lane >> 2)][nhalf] = p1;
        }
    }

#pragma unroll
    for (int i = 0; i < 8; i++) {
#pragma unroll
        for (int o = 8; o > 0; o >>= 1) {
            sx[i] += __shfl_xor_sync(0xffffffffu, sx[i], o);
            sw[i] += __shfl_xor_sync(0xffffffffu, sw[i], o);
        }
    }
    if ((t & 15) == 0) {
        const int h = t >> 4;
#pragma unroll
        for (int i = 0; i < 8; i++) {
            sxs[i * 16 + h] = sx[i];
            sws[i * 16 + h] = sw[i];
        }
    }
    __syncthreads();

    if (t < 128) {
        const float t1 = red[t][0] + red[t][1];
        const float s_ = sxs[t];
        out[mbase + t] = sws[t] + bias[0] + 0.5f * t1 - 0.5f * s_ * s_ * g_s2;
    }
}

// ---------------- launch ----------------

extern "C" void kernel_launch(void* const* d_in, const int* in_sizes, int n_in,
                              void* d_out, int out_size) {
    (void)in_sizes; (void)n_in; (void)out_size;
    const float* x = (const float*)d_in[0];
    const float* W = (const float*)d_in[1];
    const float* b = (const float*)d_in[2];
    const float* V = (const float*)d_in[3];
    float* out = (float*)d_out;

    cudaFuncSetAttribute(fm_main, cudaFuncAttributeMaxDynamicSharedMemorySize, SMEM_TOTAL);

    prep_kernel<<<64, 256>>>(V);
    s2_kernel<<<1, 128>>>();
    fm_main<<<MROWS / 128, 256, SMEM_TOTAL>>>(x, W, b, out);
}

// round 8
// speedup vs baseline: 1.4429x; 1.0233x over previous
#include <cuda_runtime.h>
#include <cuda_fp16.h>
#include <stdint.h>

// out[m] = x[m]·W + b + 0.5*||x[m]V||^2 - 0.5*(sum_i x[m,i])^2 * ||V.sum(0)||^2
// x: (16384,4096) f32, W: (1,4096) f32, b: (1,) f32, V: (4096,128) f32, out f32.
// GEMM in fp16 with fp16 accumulators (V pre-scaled by 4096); side sums exact fp32.

#define MROWS 16384
#define KDIM  4096
#define NDIM  128
#define KC    64                   // K per chunk
#define NCH   (KDIM / KC)          // 64
#define AROW  144                  // padded smem row stride (bytes)
#define ABUF  (128 * AROW)         // 18432 B per buffer

#define OF_B   (2 * ABUF)
#define OF_RED (4 * ABUF)
#define OF_SXS (OF_RED + 1024)
#define OF_SWS (OF_SXS + 512)
#define SMEM_TOTAL (OF_SWS + 512)  // 75776 B

#define VSCALE 4096.0f
#define T1SCALE (0.5f / (VSCALE * VSCALE))

__device__ __half g_Vt[(size_t)NCH * NDIM * KC];   // chunk-major [c][n][kk], fp16 of 4096*V^T
__device__ float g_spart[64 * NDIM];
__device__ float g_s2;

// ---------------- helpers ----------------

static __device__ __forceinline__ uint32_t smem_u32(const void* p) {
    uint32_t r;
    asm("{ .reg .u64 t; cvta.to.shared.u64 t, %1; cvt.u32.u64 %0, t; }"
        : "=r"(r) : "l"(p));
    return r;
}

static __device__ __forceinline__ uint32_t pack2h(float lo, float hi) {
    __half2 h = __floats2half2_rn(lo, hi);
    return *reinterpret_cast<uint32_t*>(&h);
}

// fp16 inputs, fp16 accumulators (2 packed regs)
#define MMA_F16(d0, d1, a0, a1, a2, a3, b0, b1)                            \
    asm volatile(                                                          \
        "mma.sync.aligned.m16n8k16.row.col.f16.f16.f16.f16 "               \
        "{%0,%1}, {%2,%3,%4,%5}, {%6,%7}, {%0,%1};"                        \
        : "+r"(d0), "+r"(d1)                                               \
        : "r"(a0), "r"(a1), "r"(a2), "r"(a3), "r"(b0), "r"(b1))

#define LDSM_X4(r0, r1, r2, r3, addr)                                      \
    asm volatile("ldmatrix.sync.aligned.m8n8.x4.shared.b16 "               \
                 "{%0,%1,%2,%3}, [%4];"                                    \
                 : "=r"(r0), "=r"(r1), "=r"(r2), "=r"(r3) : "r"(addr))

// ---------------- prep kernels ----------------

__global__ void prep_kernel(const float* __restrict__ V) {
    __shared__ __align__(16) __half sm[128 * 66];
    __shared__ float ps[256];
    const int t = threadIdx.x;
    const int b = blockIdx.x;
    const int k0 = b * 64;
    const int n = t & 127;
    const int half_ = t >> 7;

    float partial = 0.f;
#pragma unroll
    for (int i = 0; i < 32; i++) {
        int kk = 2 * i + half_;
        float v = V[(size_t)(k0 + kk) * NDIM + n];
        partial += v;
        sm[n * 66 + kk] = __float2half_rn(v * VSCALE);
    }
    ps[t] = partial;
    __syncthreads();
    if (t < 128) g_spart[b * 128 + t] = ps[t] + ps[t + 128];

    const int r = t >> 1, part = t & 1;
    const uint32_t* src = (const uint32_t*)((const char*)sm + r * 132 + part * 64);
    uint32_t v0[16];
#pragma unroll
    for (int i = 0; i < 16; i++) v0[i] = src[i];
    uint4* dst = (uint4*)((char*)g_Vt + (size_t)b * 16384 + (size_t)r * 128 + part * 64);
#pragma unroll
    for (int i = 0; i < 4; i++)
        dst[i] = make_uint4(v0[4*i], v0[4*i+1], v0[4*i+2], v0[4*i+3]);
}

__global__ void s2_kernel() {
    __shared__ float sh[128];
    int t = threadIdx.x;
    float s = 0.f;
    for (int b2 = 0; b2 < 64; b2++) s += g_spart[b2 * 128 + t];
    sh[t] = s * s;
    __syncthreads();
    for (int o = 64; o > 0; o >>= 1) {
        if (t < o) sh[t] += sh[t + o];
        __syncthreads();
    }
    if (t == 0) g_s2 = sh[0];
}

// ---------------- main kernel ----------------
// 256 thr = 8 warps = 4 m-strips (m32) x 2 n-halves (n64). CTA tile 128x128.
// Round-4 structure; GEMM fp16 x fp16 -> fp16 accumulators.

__global__ void __launch_bounds__(256, 1) fm_main(
    const float* __restrict__ x, const float* __restrict__ W,
    const float* __restrict__ bias, float* __restrict__ out)
{
    extern __shared__ __align__(16) char smem[];
    float (*red)[2] = (float(*)[2])(smem + OF_RED);
    float* sxs = (float*)(smem + OF_SXS);
    float* sws = (float*)(smem + OF_SWS);

    const int t = threadIdx.x;
    const int wid = t >> 5, lane = t & 31;
    const int mstrip = wid & 3;
    const int nhalf  = wid >> 2;
    const int mbase = blockIdx.x * 128;

    const uint32_t sAu = smem_u32(smem);
    const uint32_t sBu = sAu + OF_B;

    // ---- gmem pointers (coalesced)
    const char* xb = (const char*)x + ((size_t)(mbase + (t >> 4)) << 14) + (t & 15) * 16;
    const char* vb = (const char*)g_Vt + (size_t)t * 16;
    const float4* wp = (const float4*)W + (t & 15);

    // ---- STS addresses (bank-conflict free on 144B rows)
    const uint32_t asts = sAu + (t >> 4) * AROW + (t & 15) * 8;
    const uint32_t bsts = sBu + (t >> 3) * AROW + (t & 7) * 16;

    // ---- ldmatrix addresses
    const uint32_t alds = sAu + (uint32_t)(mstrip * 32 + (lane & 15)) * AROW
                        + (lane >> 4) * 16;
    const uint32_t blds = sBu + (uint32_t)(nhalf * 64 + (lane >> 4) * 8 + (lane & 7)) * AROW
                        + ((lane >> 3) & 1) * 16;

    // fp16 packed accumulators: acc[mt][nt] = {c0c1, c2c3}
    uint32_t acc[2][8][2];
#pragma unroll
    for (int i = 0; i < 2; i++)
#pragma unroll
        for (int j = 0; j < 8; j++) { acc[i][j][0] = 0u; acc[i][j][1] = 0u; }

    float sx[8], sw[8];
#pragma unroll
    for (int i = 0; i < 8; i++) { sx[i] = 0.f; sw[i] = 0.f; }

    float4 areg[8];
    uint4  breg[4];

#define LOADA(c) do {                                                       \
        _Pragma("unroll")                                                   \
        for (int i = 0; i < 8; i++)                                         \
            areg[i] = *(const float4*)(xb + (size_t)i * 262144 + (c) * 256);\
    } while (0)

#define LOADB(c) do {                                                       \
        _Pragma("unroll")                                                   \
        for (int j = 0; j < 4; j++)                                         \
            breg[j] = *(const uint4*)(vb + (size_t)(c) * 16384 + j * 4096); \
    } while (0)

#define SUMS_STS(c, buf) do {                                               \
        const float4 w4 = wp[(c) * 16];                                     \
        const uint32_t ao_ = (uint32_t)(buf) * ABUF;                        \
        _Pragma("unroll")                                                   \
        for (int i = 0; i < 8; i++) {                                       \
            const float4 q = areg[i];                                       \
            sx[i] += (q.x + q.y) + (q.z + q.w);                             \
            sw[i] += q.x * w4.x + q.y * w4.y + q.z * w4.z + q.w * w4.w;     \
            const uint32_t p0 = pack2h(q.x, q.y), p1 = pack2h(q.z, q.w);    \
            asm volatile("st.shared.v2.b32 [%0], {%1,%2};"                  \
                         :: "r"(asts + ao_ + i * 2304), "r"(p0), "r"(p1));  \
        }                                                                   \
        _Pragma("unroll")                                                   \
        for (int j = 0; j < 4; j++)                                         \
            asm volatile("st.shared.v4.b32 [%0], {%1,%2,%3,%4};"            \
                         :: "r"(bsts + ao_ + j * 4608), "r"(breg[j].x),     \
                            "r"(breg[j].y), "r"(breg[j].z), "r"(breg[j].w));\
    } while (0)

    // prologue: stage chunk 0
    LOADA(0); LOADB(0);
    SUMS_STS(0, 0);
    __syncthreads();

#pragma unroll 1
    for (int c = 0; c < NCH; c++) {
        const bool more = (c + 1 < NCH);
        if (more) { LOADA(c + 1); LOADB(c + 1); }

        const uint32_t ao = (uint32_t)(c & 1) * ABUF;
#pragma unroll
        for (int ks = 0; ks < 4; ks++) {
            uint32_t afr[2][4];
            LDSM_X4(afr[0][0], afr[0][1], afr[0][2], afr[0][3],
                    alds + ao + ks * 32);
            LDSM_X4(afr[1][0], afr[1][1], afr[1][2], afr[1][3],
                    alds + ao + ks * 32 + 16 * AROW);
            uint32_t bfr[8][2];
#pragma unroll
            for (int p = 0; p < 4; p++)
                LDSM_X4(bfr[2*p][0], bfr[2*p][1], bfr[2*p+1][0], bfr[2*p+1][1],
                        blds + ao + ks * 32 + p * 16 * AROW);
#pragma unroll
            for (int mt = 0; mt < 2; mt++)
#pragma unroll
                for (int nt = 0; nt < 8; nt++)
                    MMA_F16(acc[mt][nt][0], acc[mt][nt][1],
                            afr[mt][0], afr[mt][1], afr[mt][2], afr[mt][3],
                            bfr[nt][0], bfr[nt][1]);
        }

        if (more) SUMS_STS(c + 1, (c + 1) & 1);
        __syncthreads();
    }

    // ---------------- epilogue ----------------
#pragma unroll
    for (int mt = 0; mt < 2; mt++) {
        float p0 = 0.f, p1 = 0.f;
#pragma unroll
        for (int nt = 0; nt < 8; nt++) {
            const float2 f0 = __half22float2(*reinterpret_cast<__half2*>(&acc[mt][nt][0]));
            const float2 f1 = __half22float2(*reinterpret_cast<__half2*>(&acc[mt][nt][1]));
            p0 += f0.x * f0.x + f0.y * f0.y;
            p1 += f1.x * f1.x + f1.y * f1.y;
        }
        p0 += __shfl_xor_sync(0xffffffffu, p0, 1);
        p0 += __shfl_xor_sync(0xffffffffu, p0, 2);
        p1 += __shfl_xor_sync(0xffffffffu, p1, 1);
        p1 += __shfl_xor_sync(0xffffffffu, p1, 2);
        if ((lane & 3) == 0) {
            red[mstrip * 32 + mt * 16 + (lane >> 2)][nhalf]     = p0;
            red[mstrip * 32 + mt * 16 + 8 + (lane >> 2)][nhalf] = p1;
        }
    }

    // side sums: reduce over 16 threads sharing each row
#pragma unroll
    for (int i = 0; i < 8; i++) {
#pragma unroll
        for (int o = 8; o > 0; o >>= 1) {
            sx[i] += __shfl_xor_sync(0xffffffffu, sx[i], o);
            sw[i] += __shfl_xor_sync(0xffffffffu, sw[i], o);
        }
    }
    if ((t & 15) == 0) {
        const int h = t >> 4;
#pragma unroll
        for (int i = 0; i < 8; i++) {
            sxs[i * 16 + h] = sx[i];
            sws[i * 16 + h] = sw[i];
        }
    }
    __syncthreads();

    if (t < 128) {
        const float t1 = red[t][0] + red[t][1];
        const float s_ = sxs[t];
        out[mbase + t] = sws[t] + bias[0] + T1SCALE * t1 - 0.5f * s_ * s_ * g_s2;
    }
}

// ---------------- launch ----------------

extern "C" void kernel_launch(void* const* d_in, const int* in_sizes, int n_in,
                              void* d_out, int out_size) {
    (void)in_sizes; (void)n_in; (void)out_size;
    const float* x = (const float*)d_in[0];
    const float* W = (const float*)d_in[1];
    const float* b = (const float*)d_in[2];
    const float* V = (const float*)d_in[3];
    float* out = (float*)d_out;

    cudaFuncSetAttribute(fm_main, cudaFuncAttributeMaxDynamicSharedMemorySize, SMEM_TOTAL);

    prep_kernel<<<64, 256>>>(V);
    s2_kernel<<<1, 128>>>();
    fm_main<<<MROWS / 128, 256, SMEM_TOTAL>>>(x, W, b, out);
}